// round 3
// baseline (speedup 1.0000x reference)
#include <cuda_runtime.h>

#define BB 4
#define CHN 128
#define HH 128
#define WW 128
#define HW 16384          // HH*WW
#define K2C 1152          // CHN*9

// ---------------- scratch (device globals; allocation-free) ----------------
__device__ float g_attn [BB*CHN*HW];   // sigmoid(conv_attn)
__device__ float g_feat [BB*CHN*HW];   // raw conv_feat
__device__ float g_xatt [BB*CHN*HW];   // x_attned
__device__ float g_off  [BB*27*HW];    // 18 offsets + 9 sigmoided masks
__device__ float g_dconv[BB*CHN*HW];   // deform conv output
__device__ float g_stats[2*BB*CHN*2];  // [which][b*C+c][sum, sumsq]
__device__ float g_norm [2*BB*CHN*2];  // [which][b*C+c][mu, rstd]
__device__ float g_wt   [K2C*CHN];     // w_org transposed: [ck][co]

__device__ __forceinline__ float sigmoidf(float v) { return 1.0f/(1.0f + __expf(-v)); }

// ---------------- prep: zero stats + transpose w_org ----------------
__global__ void prep_kernel(const float* __restrict__ w_org) {
    int i = blockIdx.x*blockDim.x + threadIdx.x;
    if (i < 2*BB*CHN*2) g_stats[i] = 0.0f;
    if (i < K2C*CHN) {
        int ck = i >> 7, co = i & 127;       // g_wt[ck*128 + co]
        g_wt[i] = w_org[co*K2C + ck];
    }
}

__global__ void finalize_stats_kernel() {
    int i = blockIdx.x*blockDim.x + threadIdx.x;
    if (i >= 2*BB*CHN) return;
    float s = g_stats[2*i], q = g_stats[2*i+1];
    float mu  = s * (1.0f/HW);
    float var = q * (1.0f/HW) - mu*mu;
    g_norm[2*i]   = mu;
    g_norm[2*i+1] = rsqrtf(var + 1e-5f);
}

// ---------------- direct 3x3 conv (CIN=128) ----------------
// modes: 0 = attn (sigmoid -> g_attn), 1 = feat (raw -> g_feat, +stats),
//        2 = offmask (input g_xatt, 27 out ch: 18 raw + 9 sigmoid -> g_off)
#define MODE_ATTN 0
#define MODE_FEAT 1
#define MODE_OFFM 2

__global__ __launch_bounds__(256) void conv3x3_kernel(
    const float* __restrict__ xin,
    const float* __restrict__ w1, const float* __restrict__ b1,
    const float* __restrict__ w2, const float* __restrict__ b2,
    int mode)
{
    __shared__ float in_s[4*324];    // 4 cin x 18x18 (row stride 18)
    __shared__ float w_s [32*4*9];   // 32 co x 4 cin x 9

    const float* in = (mode == MODE_OFFM) ? g_xatt : xin;
    const int COUT  = (mode == MODE_OFFM) ? 27 : 128;

    int b   = blockIdx.z;
    int ty0 = (blockIdx.x >> 3) << 4;
    int tx0 = (blockIdx.x & 7) << 4;
    int cobase = blockIdx.y << 5;
    int tid   = threadIdx.x;
    int xcol  = tid & 15;
    int slice = tid >> 4;            // 16 slices, each owns 2 couts

    float acc0[16], acc1[16];
    #pragma unroll
    for (int r = 0; r < 16; r++) { acc0[r] = 0.f; acc1[r] = 0.f; }

    for (int chunk = 0; chunk < 32; chunk++) {
        int c0 = chunk << 2;
        __syncthreads();
        // stage input tile (4 cin x 18x18, zero-padded borders)
        for (int i = tid; i < 4*324; i += 256) {
            int ci = i / 324; int rem = i - ci*324;
            int iy = rem / 18; int ix = rem - iy*18;
            int gy = ty0 + iy - 1, gx = tx0 + ix - 1;
            float v = 0.f;
            if (gy >= 0 && gy < HH && gx >= 0 && gx < WW)
                v = in[((size_t)(b*CHN + c0 + ci))*HW + gy*WW + gx];
            in_s[i] = v;
        }
        // stage weights (32 co x 4 cin x 9)
        for (int i = tid; i < 32*4*9; i += 256) {
            int co = i / 36; int rem = i - co*36;
            int ci = rem / 9; int k = rem - ci*9;
            int cog = cobase + co;
            float wv = 0.f;
            if (mode == MODE_OFFM) {
                if (cog < 18)      wv = w1[((size_t)cog*CHN + c0 + ci)*9 + k];
                else if (cog < 27) wv = w2[((size_t)(cog-18)*CHN + c0 + ci)*9 + k];
            } else {
                wv = w1[((size_t)cog*CHN + c0 + ci)*9 + k];
            }
            w_s[i] = wv;
        }
        __syncthreads();

        #pragma unroll
        for (int ci = 0; ci < 4; ci++) {
            float wk0[9], wk1[9];
            #pragma unroll
            for (int k = 0; k < 9; k++) {
                wk0[k] = w_s[(slice*2  )*36 + ci*9 + k];
                wk1[k] = w_s[(slice*2+1)*36 + ci*9 + k];
            }
            #pragma unroll
            for (int iy = 0; iy < 18; iy++) {
                float v0 = in_s[ci*324 + iy*18 + xcol];
                float v1 = in_s[ci*324 + iy*18 + xcol + 1];
                float v2 = in_s[ci*324 + iy*18 + xcol + 2];
                #pragma unroll
                for (int ky = 0; ky < 3; ky++) {
                    int r = iy - ky;
                    if (r >= 0 && r < 16) {
                        acc0[r] += v0*wk0[ky*3+0] + v1*wk0[ky*3+1] + v2*wk0[ky*3+2];
                        acc1[r] += v0*wk1[ky*3+0] + v1*wk1[ky*3+1] + v2*wk1[ky*3+2];
                    }
                }
            }
        }
    }

    // epilogue
    #pragma unroll
    for (int co2 = 0; co2 < 2; co2++) {
        int cog = cobase + slice*2 + co2;
        bool active = (cog < COUT);
        float bv = 0.f;
        if (active) {
            if (mode == MODE_OFFM) bv = (cog < 18) ? b1[cog] : b2[cog-18];
            else                   bv = b1[cog];
        }
        float* ob = (mode == MODE_ATTN) ? g_attn : (mode == MODE_FEAT) ? g_feat : g_off;
        size_t obase = ((size_t)(b*COUT + (active?cog:0)))*HW + (size_t)ty0*WW + tx0 + xcol;
        float ps = 0.f, pq = 0.f;
        #pragma unroll
        for (int r = 0; r < 16; r++) {
            float v = ((co2 == 0) ? acc0[r] : acc1[r]) + bv;
            if (mode == MODE_ATTN) v = sigmoidf(v);
            if (mode == MODE_OFFM && cog >= 18) v = sigmoidf(v);
            if (active) ob[obase + (size_t)r*WW] = v;
            ps += v; pq += v*v;
        }
        if (mode == MODE_FEAT) {
            #pragma unroll
            for (int m = 1; m < 16; m <<= 1) {
                ps += __shfl_xor_sync(0xffffffffu, ps, m);
                pq += __shfl_xor_sync(0xffffffffu, pq, m);
            }
            if ((tid & 15) == 0) {
                atomicAdd(&g_stats[(b*CHN + cog)*2 + 0], ps);
                atomicAdd(&g_stats[(b*CHN + cog)*2 + 1], pq);
            }
        }
    }
}

// ---------------- x_attned = lrelu(IN(feat)) * attn ----------------
__global__ void xatt_kernel() {
    int i = blockIdx.x*blockDim.x + threadIdx.x;   // over float4s, 2097152 total
    int plane = i >> 12;                           // / 4096
    float mu = g_norm[2*plane], rs = g_norm[2*plane+1];
    float4 f = ((const float4*)g_feat)[i];
    float4 a = ((const float4*)g_attn)[i];
    float4 o; float v;
    v = (f.x - mu)*rs; v = v > 0.f ? v : 0.2f*v; o.x = v*a.x;
    v = (f.y - mu)*rs; v = v > 0.f ? v : 0.2f*v; o.y = v*a.y;
    v = (f.z - mu)*rs; v = v > 0.f ? v : 0.2f*v; o.z = v*a.z;
    v = (f.w - mu)*rs; v = v > 0.f ? v : 0.2f*v; o.w = v*a.w;
    ((float4*)g_xatt)[i] = o;
}

// ---------------- deformable conv: sample + per-pixel GEMM ----------------
// block: 16 pixels (one row segment), 256 threads, dyn smem 80384 B
__global__ __launch_bounds__(256) void deform_kernel(const float* __restrict__ b_org)
{
    extern __shared__ float sm[];
    float* samp = sm;                      // [1152][16]
    float* cw   = sm + K2C*16;             // [4][144]
    int*   cidx = (int*)(cw + 576);        // [4][144]
    float* red  = cw + 576 + 576;          // [512]

    int b = blockIdx.z, h = blockIdx.y, wseg = blockIdx.x;
    int t = threadIdx.x;

    if (t < 144) {
        int k = t >> 4, p = t & 15;
        int w0 = (wseg << 4) + p;
        const float* ob = g_off + (size_t)b*27*HW + h*WW + w0;
        float dy = ob[(size_t)(2*k  )*HW];
        float dx = ob[(size_t)(2*k+1)*HW];
        float mk = ob[(size_t)(18+k )*HW];
        float yy = dy + (float)(h  + k/3 - 1);
        float xx = dx + (float)(w0 + k%3 - 1);
        float y0f = floorf(yy), x0f = floorf(xx);
        float wy = yy - y0f, wx = xx - x0f;
        int y0 = (int)y0f, x0 = (int)x0f;
        #pragma unroll
        for (int cnr = 0; cnr < 4; cnr++) {
            int ddy = cnr >> 1, ddx = cnr & 1;
            int yi = y0 + ddy, xi = x0 + ddx;
            bool valid = (yi >= 0) && (yi < HH) && (xi >= 0) && (xi < WW);
            int yc = min(max(yi, 0), HH-1);
            int xc = min(max(xi, 0), WW-1);
            float wgt = (ddy ? wy : 1.f - wy) * (ddx ? wx : 1.f - wx) * mk;
            if (!valid) wgt = 0.f;
            cw  [cnr*144 + t] = wgt;
            cidx[cnr*144 + t] = yc*WW + xc;
        }
    }
    __syncthreads();

    if (t < 144) {
        int k = t >> 4, p = t & 15;
        int   i0 = cidx[t], i1 = cidx[144+t], i2 = cidx[288+t], i3 = cidx[432+t];
        float f0 = cw[t], f1 = cw[144+t], f2 = cw[288+t], f3 = cw[432+t];
        const float* base = g_xatt + (size_t)b*CHN*HW;
        float* sp = samp + k*16 + p;       // samp[(c*9+k)*16+p] = sp[c*144]
        #pragma unroll 4
        for (int c = 0; c < CHN; c++) {
            const float* pl = base + (size_t)c*HW;
            sp[c*144] = f0*pl[i0] + f1*pl[i1] + f2*pl[i2] + f3*pl[i3];
        }
    }
    __syncthreads();

    // GEMM: out[co][p] = sum_ck w_t[ck][co] * samp[ck][p]
    int co = t & 127, pg = t >> 7;
    float acc[8];
    #pragma unroll
    for (int j = 0; j < 8; j++) acc[j] = 0.f;
    const float* wp  = g_wt + co;
    const float* spp = samp + pg*8;
    #pragma unroll 4
    for (int ck = 0; ck < K2C; ck++) {
        float  wv = wp[(size_t)ck*CHN];
        float4 s0 = *(const float4*)(spp + ck*16);
        float4 s1 = *(const float4*)(spp + ck*16 + 4);
        acc[0] += wv*s0.x; acc[1] += wv*s0.y; acc[2] += wv*s0.z; acc[3] += wv*s0.w;
        acc[4] += wv*s1.x; acc[5] += wv*s1.y; acc[6] += wv*s1.z; acc[7] += wv*s1.w;
    }
    float bv = b_org[co];
    float ps = 0.f, pq = 0.f;
    float4 o0, o1;
    o0.x = acc[0]+bv; o0.y = acc[1]+bv; o0.z = acc[2]+bv; o0.w = acc[3]+bv;
    o1.x = acc[4]+bv; o1.y = acc[5]+bv; o1.z = acc[6]+bv; o1.w = acc[7]+bv;
    ps = o0.x+o0.y+o0.z+o0.w + o1.x+o1.y+o1.z+o1.w;
    pq = o0.x*o0.x+o0.y*o0.y+o0.z*o0.z+o0.w*o0.w
       + o1.x*o1.x+o1.y*o1.y+o1.z*o1.z+o1.w*o1.w;
    float* op = g_dconv + ((size_t)(b*CHN + co))*HW + h*WW + (wseg<<4) + pg*8;
    *(float4*)op       = o0;
    *(float4*)(op + 4) = o1;

    red[t] = ps; red[256 + t] = pq;
    __syncthreads();
    if (t < 128) {
        float s = red[t]       + red[t+128];
        float q = red[256 + t] + red[384 + t];
        atomicAdd(&g_stats[(BB*CHN + b*CHN + t)*2 + 0], s);
        atomicAdd(&g_stats[(BB*CHN + b*CHN + t)*2 + 1], q);
    }
}

// ---------------- final: out = xatt + lrelu(IN(dconv)) * (1 - attn) -------
__global__ void final_kernel(float* __restrict__ out) {
    int i = blockIdx.x*blockDim.x + threadIdx.x;
    int plane = i >> 12;
    float mu = g_norm[2*(BB*CHN + plane)], rs = g_norm[2*(BB*CHN + plane)+1];
    float4 d  = ((const float4*)g_dconv)[i];
    float4 a  = ((const float4*)g_attn)[i];
    float4 xa = ((const float4*)g_xatt)[i];
    float4 o; float v;
    v = (d.x - mu)*rs; v = v > 0.f ? v : 0.2f*v; o.x = xa.x + v*(1.f - a.x);
    v = (d.y - mu)*rs; v = v > 0.f ? v : 0.2f*v; o.y = xa.y + v*(1.f - a.y);
    v = (d.z - mu)*rs; v = v > 0.f ? v : 0.2f*v; o.z = xa.z + v*(1.f - a.z);
    v = (d.w - mu)*rs; v = v > 0.f ? v : 0.2f*v; o.w = xa.w + v*(1.f - a.w);
    ((float4*)out)[i] = o;
}

// ---------------- launch ----------------
extern "C" void kernel_launch(void* const* d_in, const int* in_sizes, int n_in,
                              void* d_out, int out_size) {
    const float* x      = (const float*)d_in[0];
    const float* w_attn = (const float*)d_in[1];
    const float* b_attn = (const float*)d_in[2];
    const float* w_feat = (const float*)d_in[3];
    const float* b_feat = (const float*)d_in[4];
    const float* w_org  = (const float*)d_in[5];
    const float* b_org  = (const float*)d_in[6];
    const float* w_off  = (const float*)d_in[7];
    const float* b_off  = (const float*)d_in[8];
    const float* w_mask = (const float*)d_in[9];
    const float* b_mask = (const float*)d_in[10];
    float* out = (float*)d_out;

    const int DSMEM = (K2C*16 + 576 + 576 + 512) * 4;  // 80384 B
    cudaFuncSetAttribute(deform_kernel, cudaFuncAttributeMaxDynamicSharedMemorySize, DSMEM);

    prep_kernel<<<576, 256>>>(w_org);

    dim3 cgrid(64, 4, 4);
    conv3x3_kernel<<<cgrid, 256>>>(x, w_attn, b_attn, nullptr, nullptr, MODE_ATTN);
    conv3x3_kernel<<<cgrid, 256>>>(x, w_feat, b_feat, nullptr, nullptr, MODE_FEAT);
    finalize_stats_kernel<<<4, 256>>>();
    xatt_kernel<<<8192, 256>>>();

    dim3 ogrid(64, 1, 4);
    conv3x3_kernel<<<ogrid, 256>>>(nullptr, w_off, b_off, w_mask, b_mask, MODE_OFFM);

    dim3 dgrid(8, 128, 4);
    deform_kernel<<<dgrid, 256, DSMEM>>>(b_org);
    finalize_stats_kernel<<<4, 256>>>();
    final_kernel<<<8192, 256>>>(out);
}

// round 4
// speedup vs baseline: 2.5099x; 2.5099x over previous
#include <cuda_runtime.h>

#define BB  4
#define CHN 128
#define HH  128
#define WW  128
#define HW  16384
#define K2C 1152
#define NPX (BB*HW)

// ---------------- scratch (device globals; allocation-free) ----------------
__device__ float g_xT   [(size_t)NPX*CHN];     // x in NHWC
__device__ float g_xattT[(size_t)NPX*CHN];     // x_attned in NHWC
__device__ float g_attn [(size_t)BB*CHN*HW];   // sigmoid(conv_attn), NCHW
__device__ float g_feat [(size_t)BB*CHN*HW];   // raw conv_feat, NCHW
__device__ float g_xatt [(size_t)BB*CHN*HW];   // x_attned, NCHW
__device__ float g_off  [(size_t)BB*27*HW];    // 18 offsets + 9 sigmoided masks
__device__ float g_dconv[(size_t)BB*CHN*HW];   // deform conv output
__device__ float g_big  [(size_t)NPX*K2C];     // im2col / sampled matrix (reused)
__device__ float g_wA[K2C*256];                // [tap*128+ci][co] attn(0-127)+feat(128-255)
__device__ float g_wt[K2C*128];                // [tap*128+ci][co] w_org
__device__ float g_wM[K2C*32];                 // [tap*128+ci][co] off(0-17)+mask(18-26)+pad
__device__ float g_biasA[256];
__device__ float g_biasM[32];
__device__ float g_biasO[128];
__device__ float g_stats[2*BB*CHN*2];
__device__ float g_norm [2*BB*CHN*2];

__device__ __forceinline__ float sigmoidf(float v) { return 1.0f/(1.0f + __expf(-v)); }

__device__ __forceinline__ void mma_tf32(float* d, const unsigned* a,
                                         unsigned b0, unsigned b1) {
    asm volatile(
        "mma.sync.aligned.m16n8k8.row.col.f32.tf32.tf32.f32 "
        "{%0,%1,%2,%3},{%4,%5,%6,%7},{%8,%9},{%0,%1,%2,%3};\n"
        : "+f"(d[0]), "+f"(d[1]), "+f"(d[2]), "+f"(d[3])
        : "r"(a[0]), "r"(a[1]), "r"(a[2]), "r"(a[3]), "r"(b0), "r"(b1));
}

// ---------------- prep: repack weights/biases, zero stats ----------------
__global__ void prep_k(const float* __restrict__ w_attn, const float* __restrict__ w_feat,
                       const float* __restrict__ w_org,  const float* __restrict__ w_off,
                       const float* __restrict__ w_mask,
                       const float* __restrict__ b_attn, const float* __restrict__ b_feat,
                       const float* __restrict__ b_org,  const float* __restrict__ b_off,
                       const float* __restrict__ b_mask)
{
    int i = blockIdx.x*256 + threadIdx.x;
    if (i < K2C*256) {
        int k = i >> 8, co = i & 255;
        int tap = k >> 7, ci = k & 127;
        g_wA[i] = (co < 128) ? w_attn[((co<<7)+ci)*9 + tap]
                             : w_feat[(((co-128)<<7)+ci)*9 + tap];
    }
    if (i < K2C*128) {
        int k = i >> 7, co = i & 127;
        int tap = k >> 7, ci = k & 127;
        g_wt[i] = w_org[((co<<7)+ci)*9 + tap];
    }
    if (i < K2C*32) {
        int k = i >> 5, co = i & 31;
        int tap = k >> 7, ci = k & 127;
        float v = 0.f;
        if (co < 18)      v = w_off [((co<<7)+ci)*9 + tap];
        else if (co < 27) v = w_mask[(((co-18)<<7)+ci)*9 + tap];
        g_wM[i] = v;
    }
    if (i < 256) g_biasA[i] = (i < 128) ? b_attn[i] : b_feat[i-128];
    if (i < 128) g_biasO[i] = b_org[i];
    if (i < 32)  g_biasM[i] = (i < 18) ? b_off[i] : (i < 27 ? b_mask[i-18] : 0.f);
    if (i < 2*BB*CHN*2) g_stats[i] = 0.f;
}

// ---------------- NCHW -> NHWC transpose of x ----------------
__global__ void transpose_k(const float* __restrict__ x) {
    int i = blockIdx.x*256 + threadIdx.x;     // == b*CHN*HW + c*HW + px
    int px = i & (HW-1);
    int c  = (i >> 14) & 127;
    int b  = i >> 21;
    g_xT[((size_t)(b << 14) + px)*CHN + c] = x[i];
}

// ---------------- im2col: NHWC src -> g_big[px][tap*128+ci] ----------------
__global__ void im2col_k(int sel) {
    const float* __restrict__ src = sel ? g_xattT : g_xT;
    const int px = blockIdx.x;                 // 65536 blocks
    const int t = threadIdx.x;                 // 288 threads
    const int tap = t >> 5, c4 = (t & 31) << 2;
    const int y = (px >> 7) & 127, xx = px & 127;
    const int ky = tap/3 - 1, kx = tap - (tap/3)*3 - 1;
    const int ny = y + ky, nx = xx + kx;
    float4 v = make_float4(0.f, 0.f, 0.f, 0.f);
    if (ny >= 0 && ny < HH && nx >= 0 && nx < WW)
        v = *(const float4*)(src + ((size_t)px + ky*WW + kx) * CHN + c4);
    *(float4*)(g_big + (size_t)px*K2C + tap*CHN + c4) = v;
}

// ---------------- generic TF32 GEMM: D[co][px] = A^T * B ----------------
// MODE 0: NCO=256 attn+feat conv; MODE 1: NCO=32 off/mask; MODE 2: NCO=128 deform
template<int NCO, int MODE>
__global__ __launch_bounds__(256) void gemm_k()
{
    __shared__ float bs[2][128*36];
    const int t = threadIdx.x;
    const int w = t >> 5, lane = t & 31, g = lane >> 2, tig = lane & 3;
    const int px0 = blockIdx.x << 7;
    constexpr int MT = (NCO == 128) ? 1 : 2;
    constexpr int NT = (NCO == 32) ? 2 : 16;
    const int co0 = (NCO == 32) ? 0 : w * 16 * MT;
    const int nb  = (NCO == 32) ? w * 2 : 0;
    const float* __restrict__ A = (MODE == 0) ? g_wA : (MODE == 2) ? g_wt : g_wM;

    float acc[MT][NT][4];
    #pragma unroll
    for (int mt = 0; mt < MT; mt++)
        #pragma unroll
        for (int nt = 0; nt < NT; nt++)
            #pragma unroll
            for (int j = 0; j < 4; j++) acc[mt][nt][j] = 0.f;

    const int sp = t >> 3, sq = t & 7;
    const float* bsrc = g_big + (size_t)px0 * K2C + sq*4;

    // prologue: stage chunk 0
    {
        float4 cur[4];
        #pragma unroll
        for (int j = 0; j < 4; j++)
            cur[j] = *(const float4*)(bsrc + (size_t)(sp + j*32)*K2C);
        #pragma unroll
        for (int j = 0; j < 4; j++)
            *(float4*)&bs[0][(sp + j*32)*36 + sq*4] = cur[j];
    }
    __syncthreads();

    for (int c = 0; c < 36; c++) {
        const int kc = c << 5;
        float4 nxt[4];
        if (c < 35) {
            #pragma unroll
            for (int j = 0; j < 4; j++)
                nxt[j] = *(const float4*)(bsrc + (size_t)(sp + j*32)*K2C + kc + 32);
        }
        const float* bb = bs[c & 1];
        #pragma unroll
        for (int ks = 0; ks < 4; ks++) {
            const int k0 = kc + ks*8;
            unsigned a[MT][4];
            #pragma unroll
            for (int mt = 0; mt < MT; mt++) {
                const float* ap = A + (size_t)k0*NCO + co0 + mt*16 + g;
                a[mt][0] = __float_as_uint(ap[tig*NCO]);
                a[mt][1] = __float_as_uint(ap[tig*NCO + 8]);
                a[mt][2] = __float_as_uint(ap[(tig+4)*NCO]);
                a[mt][3] = __float_as_uint(ap[(tig+4)*NCO + 8]);
            }
            #pragma unroll
            for (int nt = 0; nt < NT; nt++) {
                const float* bp = bb + ((nb+nt)*8 + g)*36 + ks*8 + tig;
                unsigned b0 = __float_as_uint(bp[0]);
                unsigned b1 = __float_as_uint(bp[4]);
                #pragma unroll
                for (int mt = 0; mt < MT; mt++)
                    mma_tf32(acc[mt][nt], a[mt], b0, b1);
            }
        }
        if (c < 35) {
            #pragma unroll
            for (int j = 0; j < 4; j++)
                *(float4*)&bs[(c+1)&1][(sp + j*32)*36 + sq*4] = nxt[j];
            __syncthreads();
        }
    }

    // ---- epilogue ----
    const int bI = px0 >> 14, prem = px0 & (HW-1);
    #pragma unroll
    for (int mt = 0; mt < MT; mt++) {
        #pragma unroll
        for (int r = 0; r < 2; r++) {
            const int co = co0 + mt*16 + r*8 + g;
            float bv = 0.f, s = 0.f, q = 0.f;
            float* plane = nullptr;
            bool dostats = false;
            int sidx = 0;
            if (MODE == 0) {
                bv = g_biasA[co];
                if (co < 128) plane = g_attn + ((size_t)(bI*CHN + co) << 14);
                else {
                    plane = g_feat + ((size_t)(bI*CHN + co - 128) << 14);
                    dostats = true; sidx = (bI*CHN + co - 128)*2;
                }
            } else if (MODE == 2) {
                bv = g_biasO[co];
                plane = g_dconv + ((size_t)(bI*CHN + co) << 14);
                dostats = true; sidx = (BB*CHN + bI*CHN + co)*2;
            } else {
                bv = g_biasM[co];
                if (co < 27) plane = g_off + ((size_t)(bI*27 + co) << 14);
            }
            #pragma unroll
            for (int nt = 0; nt < NT; nt++) {
                float v0 = acc[mt][nt][r*2]   + bv;
                float v1 = acc[mt][nt][r*2+1] + bv;
                if (MODE == 0 && co < 128)  { v0 = sigmoidf(v0); v1 = sigmoidf(v1); }
                if (MODE == 1 && co >= 18)  { v0 = sigmoidf(v0); v1 = sigmoidf(v1); }
                const int col = (nb + nt)*8 + 2*tig;
                if (plane) {
                    float2 o = make_float2(v0, v1);
                    *(float2*)&plane[prem + col] = o;
                }
                s += v0 + v1; q += v0*v0 + v1*v1;
            }
            if (dostats) {
                s += __shfl_xor_sync(0xffffffffu, s, 1);
                s += __shfl_xor_sync(0xffffffffu, s, 2);
                q += __shfl_xor_sync(0xffffffffu, q, 1);
                q += __shfl_xor_sync(0xffffffffu, q, 2);
                if (tig == 0) {
                    atomicAdd(&g_stats[sidx],   s);
                    atomicAdd(&g_stats[sidx+1], q);
                }
            }
        }
    }
}

__global__ void finalize_stats_k() {
    int i = blockIdx.x*blockDim.x + threadIdx.x;
    if (i >= 2*BB*CHN) return;
    float s = g_stats[2*i], q = g_stats[2*i+1];
    float mu  = s * (1.0f/HW);
    float var = q * (1.0f/HW) - mu*mu;
    g_norm[2*i]   = mu;
    g_norm[2*i+1] = rsqrtf(var + 1e-5f);
}

// ---- x_attned = lrelu(IN(feat)) * attn ; write NCHW + NHWC ----
__global__ void xatt_k() {
    int i = blockIdx.x*256 + threadIdx.x;      // float4 index
    int plane = i >> 12;
    float mu = g_norm[2*plane], rs = g_norm[2*plane+1];
    float4 f = ((const float4*)g_feat)[i];
    float4 a = ((const float4*)g_attn)[i];
    float4 o; float v;
    v = (f.x - mu)*rs; v = v > 0.f ? v : 0.2f*v; o.x = v*a.x;
    v = (f.y - mu)*rs; v = v > 0.f ? v : 0.2f*v; o.y = v*a.y;
    v = (f.z - mu)*rs; v = v > 0.f ? v : 0.2f*v; o.z = v*a.z;
    v = (f.w - mu)*rs; v = v > 0.f ? v : 0.2f*v; o.w = v*a.w;
    ((float4*)g_xatt)[i] = o;
    int b = plane >> 7, c = plane & 127;
    int p4 = (i & 4095) << 2;
    float* dT = g_xattT + ((size_t)(b << 14) + p4)*CHN + c;
    dT[0] = o.x; dT[CHN] = o.y; dT[2*CHN] = o.z; dT[3*CHN] = o.w;
}

// ---- deform sampling: build g_big[px][tap*128+ci] ----
__global__ __launch_bounds__(256) void gather_k()
{
    __shared__ float cw[576];
    __shared__ int   cidx[576];
    const int b = blockIdx.z, h = blockIdx.y, ws = blockIdx.x;
    const int t = threadIdx.x;

    if (t < 144) {
        const int k = t >> 4, p = t & 15;
        const int w0 = (ws << 4) + p;
        const float* ob = g_off + (((size_t)b*27) << 14) + h*WW + w0;
        float dy = ob[(size_t)(2*k  ) << 14];
        float dx = ob[(size_t)(2*k+1) << 14];
        float mk = ob[(size_t)(18+k ) << 14];
        float yy = dy + (float)(h  + k/3 - 1);
        float xx = dx + (float)(w0 + k%3 - 1);
        float y0f = floorf(yy), x0f = floorf(xx);
        float wy = yy - y0f, wx = xx - x0f;
        int y0 = (int)y0f, x0 = (int)x0f;
        #pragma unroll
        for (int cnr = 0; cnr < 4; cnr++) {
            int ddy = cnr >> 1, ddx = cnr & 1;
            int yi = y0 + ddy, xi = x0 + ddx;
            bool valid = (yi >= 0) && (yi < HH) && (xi >= 0) && (xi < WW);
            int yc = min(max(yi, 0), HH-1);
            int xc = min(max(xi, 0), WW-1);
            float wgt = (ddy ? wy : 1.f - wy) * (ddx ? wx : 1.f - wx) * mk;
            if (!valid) wgt = 0.f;
            cw  [cnr*144 + t] = wgt;
            cidx[cnr*144 + t] = yc*WW + xc;
        }
    }
    __syncthreads();

    const int ci = t & 127, hf = t >> 7;
    const float* xb = g_xattT + ((size_t)(b << 14)) * CHN + ci;
    float* dst = g_big + (size_t)((b << 14) + h*WW + (ws << 4)) * K2C + ci;
    for (int kp = hf; kp < 144; kp += 2) {
        const int k = kp >> 4, p = kp & 15;
        float f0 = cw[kp], f1 = cw[144+kp], f2 = cw[288+kp], f3 = cw[432+kp];
        int   i0 = cidx[kp], i1 = cidx[144+kp], i2 = cidx[288+kp], i3 = cidx[432+kp];
        float v = f0*xb[(size_t)i0*CHN] + f1*xb[(size_t)i1*CHN]
                + f2*xb[(size_t)i2*CHN] + f3*xb[(size_t)i3*CHN];
        dst[(size_t)p*K2C + k*CHN] = v;
    }
}

// ---- final: out = xatt + lrelu(IN(dconv)) * (1 - attn) ----
__global__ void final_k(float* __restrict__ out) {
    int i = blockIdx.x*256 + threadIdx.x;
    int plane = i >> 12;
    float mu = g_norm[2*(BB*CHN + plane)], rs = g_norm[2*(BB*CHN + plane)+1];
    float4 d  = ((const float4*)g_dconv)[i];
    float4 a  = ((const float4*)g_attn)[i];
    float4 xa = ((const float4*)g_xatt)[i];
    float4 o; float v;
    v = (d.x - mu)*rs; v = v > 0.f ? v : 0.2f*v; o.x = xa.x + v*(1.f - a.x);
    v = (d.y - mu)*rs; v = v > 0.f ? v : 0.2f*v; o.y = xa.y + v*(1.f - a.y);
    v = (d.z - mu)*rs; v = v > 0.f ? v : 0.2f*v; o.z = xa.z + v*(1.f - a.z);
    v = (d.w - mu)*rs; v = v > 0.f ? v : 0.2f*v; o.w = xa.w + v*(1.f - a.w);
    ((float4*)out)[i] = o;
}

// ---------------- launch ----------------
extern "C" void kernel_launch(void* const* d_in, const int* in_sizes, int n_in,
                              void* d_out, int out_size) {
    const float* x      = (const float*)d_in[0];
    const float* w_attn = (const float*)d_in[1];
    const float* b_attn = (const float*)d_in[2];
    const float* w_feat = (const float*)d_in[3];
    const float* b_feat = (const float*)d_in[4];
    const float* w_org  = (const float*)d_in[5];
    const float* b_org  = (const float*)d_in[6];
    const float* w_off  = (const float*)d_in[7];
    const float* b_off  = (const float*)d_in[8];
    const float* w_mask = (const float*)d_in[9];
    const float* b_mask = (const float*)d_in[10];
    float* out = (float*)d_out;

    prep_k<<<1152, 256>>>(w_attn, w_feat, w_org, w_off, w_mask,
                          b_attn, b_feat, b_org, b_off, b_mask);
    transpose_k<<<32768, 256>>>(x);
    im2col_k<<<NPX, 288>>>(0);
    gemm_k<256, 0><<<512, 256>>>();          // attn + feat conv
    finalize_stats_k<<<4, 256>>>();
    xatt_k<<<8192, 256>>>();
    im2col_k<<<NPX, 288>>>(1);
    gemm_k<32, 1><<<512, 256>>>();           // offset + mask conv
    gather_k<<<dim3(8, 128, 4), 256>>>();    // deform sampling -> g_big
    gemm_k<128, 2><<<512, 256>>>();          // deform einsum
    finalize_stats_k<<<4, 256>>>();
    final_k<<<8192, 256>>>(out);
}

// round 5
// speedup vs baseline: 3.8740x; 1.5435x over previous
#include <cuda_runtime.h>

#define BB  4
#define CHN 128
#define HH  128
#define WW  128
#define HW  16384
#define K2C 1152
#define NPX (BB*HW)

// ---------------- scratch (device globals; allocation-free) ----------------
__device__ float g_xT   [(size_t)NPX*CHN];     // x in NHWC
__device__ float g_xattT[(size_t)NPX*CHN];     // x_attned in NHWC
__device__ float g_attn [(size_t)BB*CHN*HW];   // sigmoid(conv_attn), NCHW
__device__ float g_feat [(size_t)BB*CHN*HW];   // raw conv_feat, NCHW
__device__ float g_xatt [(size_t)BB*CHN*HW];   // x_attned, NCHW
__device__ float g_off  [(size_t)BB*27*HW];    // 18 offsets + 9 sigmoided masks
__device__ float g_dconv[(size_t)BB*CHN*HW];   // deform conv output
__device__ float g_big  [(size_t)NPX*K2C];     // deform-sampled matrix
__device__ float g_wA[K2C*256];                // [k][co] attn(0-127)+feat(128-255)
__device__ float g_wt[K2C*128];                // [k][co] w_org
__device__ float g_wM[K2C*32];                 // [k][co] off(0-17)+mask(18-26)+pad
__device__ float g_biasA[256];
__device__ float g_biasM[32];
__device__ float g_biasO[128];
__device__ float g_stats[2*BB*CHN*2];
__device__ float g_norm [2*BB*CHN*2];

__device__ __forceinline__ float sigmoidf(float v) { return 1.0f/(1.0f + __expf(-v)); }

__device__ __forceinline__ void mma_tf32(float* d, const unsigned* a,
                                         unsigned b0, unsigned b1) {
    asm volatile(
        "mma.sync.aligned.m16n8k8.row.col.f32.tf32.tf32.f32 "
        "{%0,%1,%2,%3},{%4,%5,%6,%7},{%8,%9},{%0,%1,%2,%3};\n"
        : "+f"(d[0]), "+f"(d[1]), "+f"(d[2]), "+f"(d[3])
        : "r"(a[0]), "r"(a[1]), "r"(a[2]), "r"(a[3]), "r"(b0), "r"(b1));
}

__device__ __forceinline__ void cp16(unsigned dst, const void* src, int srcsize) {
    asm volatile("cp.async.cg.shared.global [%0], [%1], 16, %2;\n"
                 :: "r"(dst), "l"(src), "r"(srcsize));
}
__device__ __forceinline__ void cp_commit() { asm volatile("cp.async.commit_group;\n"); }
__device__ __forceinline__ void cp_wait0()  { asm volatile("cp.async.wait_group 0;\n"); }

// ---------------- prep: repack weights/biases, zero stats ----------------
__global__ void prep_k(const float* __restrict__ w_attn, const float* __restrict__ w_feat,
                       const float* __restrict__ w_org,  const float* __restrict__ w_off,
                       const float* __restrict__ w_mask,
                       const float* __restrict__ b_attn, const float* __restrict__ b_feat,
                       const float* __restrict__ b_org,  const float* __restrict__ b_off,
                       const float* __restrict__ b_mask)
{
    int i = blockIdx.x*256 + threadIdx.x;
    if (i < K2C*256) {
        int k = i >> 8, co = i & 255;
        int tap = k >> 7, ci = k & 127;
        g_wA[i] = (co < 128) ? w_attn[((co<<7)+ci)*9 + tap]
                             : w_feat[(((co-128)<<7)+ci)*9 + tap];
    }
    if (i < K2C*128) {
        int k = i >> 7, co = i & 127;
        int tap = k >> 7, ci = k & 127;
        g_wt[i] = w_org[((co<<7)+ci)*9 + tap];
    }
    if (i < K2C*32) {
        int k = i >> 5, co = i & 31;
        int tap = k >> 7, ci = k & 127;
        float v = 0.f;
        if (co < 18)      v = w_off [((co<<7)+ci)*9 + tap];
        else if (co < 27) v = w_mask[(((co-18)<<7)+ci)*9 + tap];
        g_wM[i] = v;
    }
    if (i < 256) g_biasA[i] = (i < 128) ? b_attn[i] : b_feat[i-128];
    if (i < 128) g_biasO[i] = b_org[i];
    if (i < 32)  g_biasM[i] = (i < 18) ? b_off[i] : (i < 27 ? b_mask[i-18] : 0.f);
    if (i < 2*BB*CHN*2) g_stats[i] = 0.f;
}

// ---------------- NCHW -> NHWC transpose of x (smem-tiled) ----------------
__global__ __launch_bounds__(256) void transpose_k(const float* __restrict__ x) {
    __shared__ float s[32][133];
    int bid = blockIdx.x;                 // b(4) x cg(4) x pg(128)
    int pg = bid & 127, cg = (bid >> 7) & 3, b = bid >> 9;
    int t = threadIdx.x;
    int px0 = pg << 7;
    #pragma unroll
    for (int j = 0; j < 16; j++) {
        int idx = t + j*256;              // 4096 elements
        int ch = idx >> 7, px = idx & 127;
        s[ch][px] = x[((size_t)(b*CHN + (cg<<5) + ch) << 14) + px0 + px];
    }
    __syncthreads();
    #pragma unroll
    for (int j = 0; j < 16; j++) {
        int idx = t + j*256;
        int px = idx >> 5, ch = idx & 31;
        g_xT[((size_t)((b<<14) + px0 + px))*CHN + (cg<<5) + ch] = s[ch][px];
    }
}

// ---------------- generic TF32 GEMM with implicit im2col ----------------
// MODE 0: attn+feat conv (B from g_xT);  MODE 1: off/mask (B from g_xattT);
// MODE 2: deform einsum (B from g_big)
template<int MODE>
__global__ __launch_bounds__(256, 2) void gemm_k()
{
    constexpr int NCO     = (MODE==0) ? 256 : (MODE==2 ? 128 : 32);
    constexpr int CO_TILE = (MODE==1) ? 32 : 128;
    constexpr int AP      = (MODE==1) ? 40 : 136;
    constexpr int MT      = (MODE==1) ? 2 : 4;
    constexpr int NT      = (MODE==1) ? 2 : 4;
    constexpr int A_BUF   = 32*AP;
    constexpr int B_BUF   = 128*36;
    extern __shared__ float sm[];
    float* as  = sm;                  // [2][32][AP]
    float* bsm = sm + 2*A_BUF;        // [2][128][36]

    const int t = threadIdx.x;
    const int wid = t >> 5, lane = t & 31, g = lane >> 2, tig = lane & 3;
    const int px0 = blockIdx.x << 7;
    const int bI = px0 >> 14, y = (px0 >> 7) & 127;
    const int co0 = (MODE==0) ? (blockIdx.y << 7) : 0;
    const float* __restrict__ Ag = (MODE==0) ? g_wA : (MODE==2 ? g_wt : g_wM);
    const float* __restrict__ srcT = (MODE==0) ? g_xT : g_xattT;

    const int cow = (MODE==1) ? 0 : ((wid >> 2) * 64);
    const int pxw = (MODE==1) ? (wid << 4) : ((wid & 3) << 5);

    float acc[MT][NT][4];
    #pragma unroll
    for (int mt = 0; mt < MT; mt++)
        #pragma unroll
        for (int nt = 0; nt < NT; nt++)
            #pragma unroll
            for (int j = 0; j < 4; j++) acc[mt][nt][j] = 0.f;

    const int bpx = t & 127, kq0 = t >> 7;

    // ---- staging helper (cp.async) ----
    auto stage = [&](int c, int buf) {
        // A chunk: 32 k-rows x CO_TILE
        if (MODE == 1) {
            int arow = t >> 3, aco = (t & 7) << 2;
            unsigned d = (unsigned)__cvta_generic_to_shared(as + buf*A_BUF + arow*AP + aco);
            cp16(d, Ag + (size_t)(c*32 + arow)*NCO + aco, 16);
        } else {
            int arow = t >> 5, aco = (t & 31) << 2;
            #pragma unroll
            for (int j = 0; j < 4; j++) {
                int r = arow + j*8;
                unsigned d = (unsigned)__cvta_generic_to_shared(as + buf*A_BUF + r*AP + aco);
                cp16(d, Ag + (size_t)(c*32 + r)*NCO + co0 + aco, 16);
            }
        }
        // B chunk: 128 px x 32 k
        if (MODE == 2) {
            const float* src = g_big + (size_t)(px0 + bpx)*K2C + c*32;
            #pragma unroll
            for (int j = 0; j < 4; j++) {
                int kq = kq0 + j*2;
                unsigned d = (unsigned)__cvta_generic_to_shared(bsm + buf*B_BUF + bpx*36 + kq*4);
                cp16(d, src + kq*4, 16);
            }
        } else {
            int tap = c >> 2, ci0 = (c & 3) << 5;
            int dy = tap/3 - 1, dxx = tap - (tap/3)*3 - 1;
            int yp = y + dy, xp = bpx + dxx;
            bool valid = ((unsigned)yp < 128u) && ((unsigned)xp < 128u);
            int sz = valid ? 16 : 0;
            const float* src = srcT + ((size_t)((bI<<14) + (valid ? (yp<<7)+xp : 0)))*CHN + ci0;
            #pragma unroll
            for (int j = 0; j < 4; j++) {
                int kq = kq0 + j*2;
                unsigned d = (unsigned)__cvta_generic_to_shared(bsm + buf*B_BUF + bpx*36 + kq*4);
                cp16(d, src + kq*4, sz);
            }
        }
    };

    stage(0, 0); cp_commit(); cp_wait0(); __syncthreads();

    for (int c = 0; c < 36; c++) {
        int buf = c & 1;
        if (c < 35) { stage(c+1, buf^1); cp_commit(); }
        const float* __restrict__ ab = as  + buf*A_BUF;
        const float* __restrict__ bb = bsm + buf*B_BUF;
        #pragma unroll
        for (int ks = 0; ks < 4; ks++) {
            unsigned a[MT][4];
            const float* ar = ab + (ks*8 + tig)*AP + cow + g;
            #pragma unroll
            for (int mt = 0; mt < MT; mt++) {
                a[mt][0] = __float_as_uint(ar[mt*16]);
                a[mt][1] = __float_as_uint(ar[mt*16 + 8]);
                a[mt][2] = __float_as_uint(ar[mt*16 + 4*AP]);
                a[mt][3] = __float_as_uint(ar[mt*16 + 4*AP + 8]);
            }
            #pragma unroll
            for (int nt = 0; nt < NT; nt++) {
                const float* bp = bb + (pxw + nt*8 + g)*36 + ks*8 + tig;
                unsigned b0 = __float_as_uint(bp[0]);
                unsigned b1 = __float_as_uint(bp[4]);
                #pragma unroll
                for (int mt = 0; mt < MT; mt++)
                    mma_tf32(acc[mt][nt], a[mt], b0, b1);
            }
        }
        if (c < 35) { cp_wait0(); __syncthreads(); }
    }

    // ---- epilogue ----
    const int prem = px0 & (HW-1);
    #pragma unroll
    for (int mt = 0; mt < MT; mt++) {
        #pragma unroll
        for (int r = 0; r < 2; r++) {
            const int coL = cow + mt*16 + r*8 + g;
            const int coG = co0 + coL;
            float bv = 0.f; float* plane = nullptr;
            bool sig = false, dostats = false; int sidx = 0;
            if (MODE == 0) {
                bv = g_biasA[coG];
                if (coG < 128) { plane = g_attn + ((size_t)(bI*CHN + coG) << 14); sig = true; }
                else {
                    plane = g_feat + ((size_t)(bI*CHN + coG - 128) << 14);
                    dostats = true; sidx = (bI*CHN + coG - 128)*2;
                }
            } else if (MODE == 2) {
                bv = g_biasO[coG];
                plane = g_dconv + ((size_t)(bI*CHN + coG) << 14);
                dostats = true; sidx = (BB*CHN + bI*CHN + coG)*2;
            } else {
                bv = g_biasM[coG];
                if (coG < 27) { plane = g_off + ((size_t)(bI*27 + coG) << 14); sig = (coG >= 18); }
            }
            float s = 0.f, q = 0.f;
            #pragma unroll
            for (int nt = 0; nt < NT; nt++) {
                float v0 = acc[mt][nt][r*2]   + bv;
                float v1 = acc[mt][nt][r*2+1] + bv;
                if (sig) { v0 = sigmoidf(v0); v1 = sigmoidf(v1); }
                int col = pxw + nt*8 + 2*tig;
                if (plane) *(float2*)&plane[prem + col] = make_float2(v0, v1);
                s += v0 + v1; q += v0*v0 + v1*v1;
            }
            if (dostats) {
                s += __shfl_xor_sync(0xffffffffu, s, 1);
                s += __shfl_xor_sync(0xffffffffu, s, 2);
                q += __shfl_xor_sync(0xffffffffu, q, 1);
                q += __shfl_xor_sync(0xffffffffu, q, 2);
                if (tig == 0) {
                    atomicAdd(&g_stats[sidx],   s);
                    atomicAdd(&g_stats[sidx+1], q);
                }
            }
        }
    }
}

__global__ void finalize_stats_k() {
    int i = blockIdx.x*blockDim.x + threadIdx.x;
    if (i >= 2*BB*CHN) return;
    float s = g_stats[2*i], q = g_stats[2*i+1];
    float mu  = s * (1.0f/HW);
    float var = q * (1.0f/HW) - mu*mu;
    g_norm[2*i]   = mu;
    g_norm[2*i+1] = rsqrtf(var + 1e-5f);
}

// ---- x_attned = lrelu(IN(feat)) * attn ; NCHW + NHWC (smem-tiled) ----
__global__ __launch_bounds__(256) void xatt_k() {
    __shared__ float s[32][133];
    int bid = blockIdx.x;
    int pg = bid & 127, cg = (bid >> 7) & 3, b = bid >> 9;
    int t = threadIdx.x;
    int px0 = pg << 7;
    #pragma unroll
    for (int j = 0; j < 16; j++) {
        int idx = t + j*256;
        int ch = idx >> 7, px = idx & 127;
        int plane = b*CHN + (cg<<5) + ch;
        size_t gi = ((size_t)plane << 14) + px0 + px;
        float mu = g_norm[2*plane], rs = g_norm[2*plane+1];
        float v = (g_feat[gi] - mu)*rs;
        v = v > 0.f ? v : 0.2f*v;
        float o = v * g_attn[gi];
        g_xatt[gi] = o;
        s[ch][px] = o;
    }
    __syncthreads();
    #pragma unroll
    for (int j = 0; j < 16; j++) {
        int idx = t + j*256;
        int px = idx >> 5, ch = idx & 31;
        g_xattT[((size_t)((b<<14) + px0 + px))*CHN + (cg<<5) + ch] = s[ch][px];
    }
}

// ---- deform sampling: build g_big[px][tap*128+ci] ----
__global__ __launch_bounds__(256) void gather_k()
{
    __shared__ float cw[576];
    __shared__ int   cidx[576];
    const int b = blockIdx.z, h = blockIdx.y, ws = blockIdx.x;
    const int t = threadIdx.x;

    if (t < 144) {
        const int k = t >> 4, p = t & 15;
        const int w0 = (ws << 4) + p;
        const float* ob = g_off + (((size_t)b*27) << 14) + h*WW + w0;
        float dy = ob[(size_t)(2*k  ) << 14];
        float dx = ob[(size_t)(2*k+1) << 14];
        float mk = ob[(size_t)(18+k ) << 14];
        float yy = dy + (float)(h  + k/3 - 1);
        float xx = dx + (float)(w0 + k%3 - 1);
        float y0f = floorf(yy), x0f = floorf(xx);
        float wy = yy - y0f, wx = xx - x0f;
        int y0 = (int)y0f, x0 = (int)x0f;
        #pragma unroll
        for (int cnr = 0; cnr < 4; cnr++) {
            int ddy = cnr >> 1, ddx = cnr & 1;
            int yi = y0 + ddy, xi = x0 + ddx;
            bool valid = (yi >= 0) && (yi < HH) && (xi >= 0) && (xi < WW);
            int yc = min(max(yi, 0), HH-1);
            int xc = min(max(xi, 0), WW-1);
            float wgt = (ddy ? wy : 1.f - wy) * (ddx ? wx : 1.f - wx) * mk;
            if (!valid) wgt = 0.f;
            cw  [cnr*144 + t] = wgt;
            cidx[cnr*144 + t] = yc*WW + xc;
        }
    }
    __syncthreads();

    const int ci = t & 127, hf = t >> 7;
    const float* xb = g_xattT + ((size_t)(b << 14)) * CHN + ci;
    float* dst = g_big + (size_t)((b << 14) + h*WW + (ws << 4)) * K2C + ci;
    for (int kp = hf; kp < 144; kp += 2) {
        const int k = kp >> 4, p = kp & 15;
        float f0 = cw[kp], f1 = cw[144+kp], f2 = cw[288+kp], f3 = cw[432+kp];
        int   i0 = cidx[kp], i1 = cidx[144+kp], i2 = cidx[288+kp], i3 = cidx[432+kp];
        float v = f0*xb[(size_t)i0*CHN] + f1*xb[(size_t)i1*CHN]
                + f2*xb[(size_t)i2*CHN] + f3*xb[(size_t)i3*CHN];
        dst[(size_t)p*K2C + k*CHN] = v;
    }
}

// ---- final: out = xatt + lrelu(IN(dconv)) * (1 - attn) ----
__global__ void final_k(float* __restrict__ out) {
    int i = blockIdx.x*256 + threadIdx.x;
    int plane = i >> 12;
    float mu = g_norm[2*(BB*CHN + plane)], rs = g_norm[2*(BB*CHN + plane)+1];
    float4 d  = ((const float4*)g_dconv)[i];
    float4 a  = ((const float4*)g_attn)[i];
    float4 xa = ((const float4*)g_xatt)[i];
    float4 o; float v;
    v = (d.x - mu)*rs; v = v > 0.f ? v : 0.2f*v; o.x = xa.x + v*(1.f - a.x);
    v = (d.y - mu)*rs; v = v > 0.f ? v : 0.2f*v; o.y = xa.y + v*(1.f - a.y);
    v = (d.z - mu)*rs; v = v > 0.f ? v : 0.2f*v; o.z = xa.z + v*(1.f - a.z);
    v = (d.w - mu)*rs; v = v > 0.f ? v : 0.2f*v; o.w = xa.w + v*(1.f - a.w);
    ((float4*)out)[i] = o;
}

// ---------------- launch ----------------
extern "C" void kernel_launch(void* const* d_in, const int* in_sizes, int n_in,
                              void* d_out, int out_size) {
    const float* x      = (const float*)d_in[0];
    const float* w_attn = (const float*)d_in[1];
    const float* b_attn = (const float*)d_in[2];
    const float* w_feat = (const float*)d_in[3];
    const float* b_feat = (const float*)d_in[4];
    const float* w_org  = (const float*)d_in[5];
    const float* b_org  = (const float*)d_in[6];
    const float* w_off  = (const float*)d_in[7];
    const float* b_off  = (const float*)d_in[8];
    const float* w_mask = (const float*)d_in[9];
    const float* b_mask = (const float*)d_in[10];
    float* out = (float*)d_out;

    const int SM_BIG   = (2*32*136 + 2*128*36)*4;   // 71680
    const int SM_SMALL = (2*32*40  + 2*128*36)*4;   // 47104
    cudaFuncSetAttribute(gemm_k<0>, cudaFuncAttributeMaxDynamicSharedMemorySize, SM_BIG);
    cudaFuncSetAttribute(gemm_k<1>, cudaFuncAttributeMaxDynamicSharedMemorySize, SM_SMALL);
    cudaFuncSetAttribute(gemm_k<2>, cudaFuncAttributeMaxDynamicSharedMemorySize, SM_BIG);

    prep_k<<<1152, 256>>>(w_attn, w_feat, w_org, w_off, w_mask,
                          b_attn, b_feat, b_org, b_off, b_mask);
    transpose_k<<<2048, 256>>>(x);
    gemm_k<0><<<dim3(512, 2), 256, SM_BIG>>>();    // attn + feat conv
    finalize_stats_k<<<4, 256>>>();
    xatt_k<<<2048, 256>>>();
    gemm_k<1><<<dim3(512, 1), 256, SM_SMALL>>>();  // offset + mask conv
    gather_k<<<dim3(8, 128, 4), 256>>>();          // deform sampling -> g_big
    gemm_k<2><<<dim3(512, 1), 256, SM_BIG>>>();    // deform einsum
    finalize_stats_k<<<4, 256>>>();
    final_k<<<8192, 256>>>(out);
}